// round 16
// baseline (speedup 1.0000x reference)
#include <cuda_runtime.h>
#include <cuda_fp16.h>

#define D 128
#define NMAX 50048               // 782 * 64, covers MLP grid padding
#define PAD 64                   // bucket slots per dst
#define HASH_SIZE (1u << 21)
#define OVF_MAX 4096

// ---------------- device-global scratch (no allocations allowed) ------------
__device__ unsigned long long g_hash[HASH_SIZE];      // gen-tagged, never cleared
__device__ unsigned int g_gen;
__device__ uint2 g_nf16[(size_t)NMAX * D / 4];        // 12.8 MB fp16 mirror
__device__ int g_cnt[NMAX];
__device__ int g_bucket[(size_t)NMAX * PAD];          // 12.8 MB
__device__ int g_ovf[OVF_MAX * 2];
__device__ int g_ovf_cnt;
__device__ int g_idx64;

// ---------------- packed f32x2 helpers (Blackwell FFMA2) --------------------
__device__ __forceinline__ unsigned long long ffma2(unsigned long long a,
                                                    unsigned long long b,
                                                    unsigned long long c) {
    unsigned long long d;
    asm("fma.rn.f32x2 %0, %1, %2, %3;" : "=l"(d) : "l"(a), "l"(b), "l"(c));
    return d;
}
__device__ __forceinline__ unsigned long long pack2(float lo, float hi) {
    unsigned long long r;
    asm("mov.b64 %0, {%1, %2};" : "=l"(r) : "f"(lo), "f"(hi));
    return r;
}
__device__ __forceinline__ void unpack2(unsigned long long v, float& lo, float& hi) {
    asm("mov.b64 {%0, %1}, %2;" : "=f"(lo), "=f"(hi) : "l"(v));
}
__device__ __forceinline__ __half2 h2_from_u32(unsigned int u) {
    return reinterpret_cast<const __half2&>(u);
}
__device__ __forceinline__ unsigned int u32_from_h2(__half2 h) {
    return reinterpret_cast<const unsigned int&>(h);
}

// ---------------- cp.async helpers (LDGSTS, sm_80+) --------------------------
__device__ __forceinline__ unsigned int smem_u32(const void* p) {
    unsigned int a;
    asm("{ .reg .u64 t; cvta.to.shared.u64 t, %1; cvt.u32.u64 %0, t; }"
        : "=r"(a) : "l"(p));
    return a;
}
__device__ __forceinline__ void cp_async16(unsigned int daddr, const void* src) {
    asm volatile("cp.async.cg.shared.global [%0], [%1], 16;"
                 :: "r"(daddr), "l"(src));
}
__device__ __forceinline__ void cp_commit() {
    asm volatile("cp.async.commit_group;" ::: "memory");
}
template <int N> __device__ __forceinline__ void cp_wait() {
    asm volatile("cp.async.wait_group %0;" :: "n"(N) : "memory");
}

// ---- phase 0: zero counts, build fp16 mirror, detect index dtype -----------
__global__ void __launch_bounds__(256)
k_setup(const float4* __restrict__ nf, const unsigned int* __restrict__ src,
        int n4) {
    int i = blockIdx.x * blockDim.x + threadIdx.x;
    if (i < n4) {
        float4 a = nf[i];
        uint2 o;
        o.x = u32_from_h2(__float22half2_rn(make_float2(a.x, a.y)));
        o.y = u32_from_h2(__float22half2_rn(make_float2(a.z, a.w)));
        g_nf16[i] = o;
    }
    if (i < NMAX) g_cnt[i] = 0;
    if (i == 0) {
        g_ovf_cnt = 0;
        g_gen = g_gen + 1;
        int is64 = 1;
#pragma unroll
        for (int k = 0; k < 8; k++)
            if (src[2 * k + 1] != 0u) is64 = 0;
        g_idx64 = is64;
    }
}

// ---- phase 1: fused dedup + bucket fill (thread per edge) ------------------
__global__ void __launch_bounds__(256)
k_dedup_fill(const void* __restrict__ srcp, const void* __restrict__ dstp,
             int nE) {
    int e = blockIdx.x * blockDim.x + threadIdx.x;
    if (e >= nE) return;
    int s, d;
    if (g_idx64) {
        s = (int)((const long long*)srcp)[e];
        d = (int)((const long long*)dstp)[e];
    } else {
        s = ((const int*)srcp)[e];
        d = ((const int*)dstp)[e];
    }

    unsigned int gen = g_gen;
    unsigned int key = ((unsigned)s << 16) | (unsigned)d;
    unsigned long long want = ((unsigned long long)gen << 32) | key;
    unsigned int slot = (key * 0x9E3779B1u) >> (32 - 21);

    for (;;) {
        unsigned long long cur;
        asm volatile("ld.global.cg.u64 %0, [%1];"
                     : "=l"(cur) : "l"(&g_hash[slot]));
        if (cur == want) return;
        if ((unsigned int)(cur >> 32) != gen) {
            unsigned long long prev = atomicCAS(&g_hash[slot], cur, want);
            if (prev == cur) break;
            if (prev == want) return;
            if ((unsigned int)(prev >> 32) != gen) continue;
        }
        slot = (slot + 1) & (HASH_SIZE - 1);
    }
    int pos = atomicAdd(&g_cnt[d], 1);
    if (pos < PAD) {
        g_bucket[(size_t)d * PAD + pos] = s;
    } else {
        int o = atomicAdd(&g_ovf_cnt, 1);
        if (o < OVF_MAX) { g_ovf[2 * o] = s; g_ovf[2 * o + 1] = d; }
    }
}

// ---- phase 2: fused gather-aggregate + 2-layer MLP --------------------------
// Gather prologue does k_agg's job for this block's 64 rows, writing cols
// 0-63 -> sH and cols 64-127 -> sH1 (native position; sH1 is free until the
// layer-1 epilogue, and each warp reads/writes only its own 8 rows).
// W tiles double-buffer through sWa/sWb via cp.async, hidden behind the
// gather and FFMA2 phases. smem: 32+32+16+32 = 112KB -> 2 blocks/SM.
#define MLP_INNER(SW, HROW, STRIDE)                                        \
    _Pragma("unroll 2")                                                    \
    for (int k0 = 0; k0 < 64; k0 += 4) {                                   \
        float4 h4[8];                                                      \
        _Pragma("unroll")                                                  \
        for (int i = 0; i < 8; i++)                                        \
            h4[i] = *(const float4*)((HROW) + i * (STRIDE) + k0);          \
        _Pragma("unroll")                                                  \
        for (int kk = 0; kk < 4; kk++) {                                   \
            ulonglong2 wv =                                                \
                *(const ulonglong2*)((SW) + (k0 + kk) * D + x * 4);        \
            _Pragma("unroll")                                              \
            for (int i = 0; i < 8; i++) {                                  \
                float hk = (&h4[i].x)[kk];                                 \
                unsigned long long h2 = pack2(hk, hk);                     \
                a01[i] = ffma2(h2, wv.x, a01[i]);                          \
                a23[i] = ffma2(h2, wv.y, a23[i]);                          \
            }                                                              \
        }                                                                  \
    }

__device__ __forceinline__ void cpW(float* dst, const float* src, int tid) {
    unsigned int d0 = smem_u32(dst);
    const float4* s4 = (const float4*)src;
#pragma unroll
    for (int i = 0; i < 8; i++)
        cp_async16(d0 + (tid + 256 * i) * 16, &s4[tid + 256 * i]);
}

__global__ void __launch_bounds__(256)
k_mlp(const float* __restrict__ nfeats, const float* __restrict__ alpha,
      const float* __restrict__ W1, const float* __restrict__ b1,
      const float* __restrict__ W2, const float* __restrict__ b2,
      float* __restrict__ out, int nrows) {
    extern __shared__ float smem[];
    float* sWa = smem;                 // 8192 floats
    float* sWb = smem + 8192;          // 8192 floats
    float* sH  = smem + 16384;         // 4096 floats (64 rows x cols 0-63)
    float* sH1 = smem + 20480;         // 8192 floats (64 rows x 128 cols)

    int tid = threadIdx.x;
    int x = tid & 31;
    int y = tid >> 5;
    int lane = x;                      // lane id within warp
    int row0 = blockIdx.x * 64;

    // start W1 prefetch immediately (hidden behind the gather)
    cpW(sWa, W1, tid);                 // g0: W1 k-half 0
    cp_commit();
    cpW(sWb, W1 + 64 * D, tid);        // g1: W1 k-half 1
    cp_commit();

    // ---- gather prologue: aggregate this block's 64 rows -------------------
    {
        const float4* nf4 = (const float4*)nfeats;
        float sc = 1.0f + alpha[0];
        int novf = g_ovf_cnt;
        if (novf > OVF_MAX) novf = OVF_MAX;

        for (int i = 0; i < 8; i++) {
            int r = y * 8 + i;
            int gr = row0 + r;
            if (gr >= nrows) continue;     // padded rows: smem garbage, guarded at store

            float4 a = nf4[(size_t)gr * 32 + lane];
            float4 acc = make_float4(a.x * sc, a.y * sc, a.z * sc, a.w * sc);

            int cnt = g_cnt[gr];
            if (cnt > PAD) cnt = PAD;
            const int* bk = &g_bucket[(size_t)gr * PAD];

#define ACC_H8(u)                                                         \
    do {                                                                  \
        float2 f0 = __half22float2(h2_from_u32((u).x));                   \
        float2 f1 = __half22float2(h2_from_u32((u).y));                   \
        acc.x += f0.x; acc.y += f0.y; acc.z += f1.x; acc.w += f1.y;       \
    } while (0)
            int j = 0;
            for (; j + 4 <= cnt; j += 4) {
                int s0 = bk[j], s1 = bk[j + 1], s2 = bk[j + 2], s3 = bk[j + 3];
                uint2 v0 = g_nf16[(size_t)s0 * 32 + lane];
                uint2 v1 = g_nf16[(size_t)s1 * 32 + lane];
                uint2 v2 = g_nf16[(size_t)s2 * 32 + lane];
                uint2 v3 = g_nf16[(size_t)s3 * 32 + lane];
                ACC_H8(v0); ACC_H8(v1); ACC_H8(v2); ACC_H8(v3);
            }
            for (; j < cnt; j++) {
                uint2 v0 = g_nf16[(size_t)bk[j] * 32 + lane];
                ACC_H8(v0);
            }
#undef ACC_H8
            if (novf > 0) {
                for (int k = 0; k < novf; k++) {
                    if (g_ovf[2 * k + 1] == gr) {
                        int s = g_ovf[2 * k];
                        float4 u = nf4[(size_t)s * 32 + lane];
                        acc.x += u.x; acc.y += u.y; acc.z += u.z; acc.w += u.w;
                    }
                }
            }
            // cols 0-63 -> sH (stride 64); cols 64-127 -> sH1 native (stride 128)
            if (lane < 16) *(float4*)(sH + r * 64 + lane * 4) = acc;
            else           *(float4*)(sH1 + r * D + lane * 4) = acc;
        }
    }
    __syncwarp();   // own-row smem visibility within warp

    unsigned long long a01[8], a23[8];
    {
        float4 bv = *(const float4*)(b1 + x * 4);
        unsigned long long i01 = pack2(bv.x, bv.y), i23 = pack2(bv.z, bv.w);
#pragma unroll
        for (int i = 0; i < 8; i++) { a01[i] = i01; a23[i] = i23; }
    }

    cp_wait<1>();              // g0 done (sWa = W1h0)
    __syncthreads();
    {   // layer 1, phase 0: cols of W1 k 0-63, h from sH
        const float* hrow = sH + y * 8 * 64;
        MLP_INNER(sWa, hrow, 64)
    }
    cp_wait<0>();              // g1 done (sWb = W1h1)
    __syncthreads();           // all warps done reading sWa
    cpW(sWa, W2, tid);         // g2: W2 k-half 0 (background)
    cp_commit();
    {   // layer 1, phase 1: W1 k 64-127, h from sH1 high cols
        const float* hrow = sH1 + y * 8 * D + 64;
        MLP_INNER(sWb, hrow, D)
    }

    // epilogue layer 1 -> sH1 (own rows; read back by same warp)
#pragma unroll
    for (int i = 0; i < 8; i++) {
        float f0, f1, f2, f3;
        unpack2(a01[i], f0, f1); unpack2(a23[i], f2, f3);
        *(float4*)(sH1 + (y * 8 + i) * D + x * 4) =
            make_float4(fmaxf(f0, 0.f), fmaxf(f1, 0.f),
                        fmaxf(f2, 0.f), fmaxf(f3, 0.f));
    }
    __syncwarp();

    {
        float4 bv = *(const float4*)(b2 + x * 4);
        unsigned long long i01 = pack2(bv.x, bv.y), i23 = pack2(bv.z, bv.w);
#pragma unroll
        for (int i = 0; i < 8; i++) { a01[i] = i01; a23[i] = i23; }
    }

    cp_wait<0>();              // g2 done (sWa = W2h0)
    __syncthreads();           // all warps done reading sWb
    cpW(sWb, W2 + 64 * D, tid);    // g3: W2 k-half 1 (background)
    cp_commit();
    {   // layer 2, phase 0: W2 k 0-63, h1 low cols
        const float* hrow = sH1 + y * 8 * D;
        MLP_INNER(sWa, hrow, D)
    }
    cp_wait<0>();              // g3 done (sWb = W2h1)
    __syncthreads();
    {   // layer 2, phase 1: W2 k 64-127, h1 high cols
        const float* hrow = sH1 + y * 8 * D + 64;
        MLP_INNER(sWb, hrow, D)
    }

#pragma unroll
    for (int i = 0; i < 8; i++) {
        int gr = row0 + y * 8 + i;
        if (gr < nrows) {
            float f0, f1, f2, f3;
            unpack2(a01[i], f0, f1); unpack2(a23[i], f2, f3);
            *(float4*)(out + (size_t)gr * D + x * 4) =
                make_float4(f0, f1, f2, f3);
        }
    }
}

// ---------------- launch ----------------------------------------------------
#define MLP_SMEM (28672 * 4)     // 114688 bytes

extern "C" void kernel_launch(void* const* d_in, const int* in_sizes, int n_in,
                              void* d_out, int out_size) {
    const float* nfeats = (const float*)d_in[0];
    const void*  src    = d_in[1];
    const void*  dst    = d_in[2];
    const float* W1     = (const float*)d_in[3];
    const float* b1     = (const float*)d_in[4];
    const float* W2     = (const float*)d_in[5];
    const float* b2     = (const float*)d_in[6];
    const float* alpha  = (const float*)d_in[7];
    float* out = (float*)d_out;

    int nE    = in_sizes[1];
    int nrows = in_sizes[0] / D;
    int n4    = nrows * (D / 4);

    int setup_items = n4 > NMAX ? n4 : NMAX;
    k_setup<<<(setup_items + 255) / 256, 256>>>(
        (const float4*)nfeats, (const unsigned int*)src, n4);
    k_dedup_fill<<<(nE + 255) / 256, 256>>>(src, dst, nE);

    cudaFuncSetAttribute(k_mlp, cudaFuncAttributeMaxDynamicSharedMemorySize,
                         MLP_SMEM);
    int nblk = (nrows + 63) / 64;
    k_mlp<<<nblk, 256, MLP_SMEM>>>(nfeats, alpha, W1, b1, W2, b2, out, nrows);
}

// round 17
// speedup vs baseline: 1.1757x; 1.1757x over previous
#include <cuda_runtime.h>
#include <cuda_fp16.h>

#define D 128
#define NMAX 50048               // 782 * 64, covers MLP grid padding
#define PAD 64                   // bucket slots per dst
#define HASH_SIZE (1u << 21)
#define OVF_MAX 4096

// ---------------- device-global scratch (no allocations allowed) ------------
__device__ unsigned long long g_hash[HASH_SIZE];      // gen-tagged, never cleared
__device__ unsigned int g_gen;
__device__ float g_h[(size_t)NMAX * D];               // 25.6 MB
__device__ uint2 g_nf16[(size_t)NMAX * D / 4];        // 12.8 MB fp16 mirror
__device__ int g_cnt[NMAX];
__device__ int g_bucket[(size_t)NMAX * PAD];          // 12.8 MB
__device__ int g_ovf[OVF_MAX * 2];
__device__ int g_ovf_cnt;
__device__ int g_idx64;

// ---------------- packed f32x2 helpers (Blackwell FFMA2) --------------------
__device__ __forceinline__ unsigned long long ffma2(unsigned long long a,
                                                    unsigned long long b,
                                                    unsigned long long c) {
    unsigned long long d;
    asm("fma.rn.f32x2 %0, %1, %2, %3;" : "=l"(d) : "l"(a), "l"(b), "l"(c));
    return d;
}
__device__ __forceinline__ unsigned long long pack2(float lo, float hi) {
    unsigned long long r;
    asm("mov.b64 %0, {%1, %2};" : "=l"(r) : "f"(lo), "f"(hi));
    return r;
}
__device__ __forceinline__ void unpack2(unsigned long long v, float& lo, float& hi) {
    asm("mov.b64 {%0, %1}, %2;" : "=f"(lo), "=f"(hi) : "l"(v));
}
__device__ __forceinline__ __half2 h2_from_u32(unsigned int u) {
    return reinterpret_cast<const __half2&>(u);
}
__device__ __forceinline__ unsigned int u32_from_h2(__half2 h) {
    return reinterpret_cast<const unsigned int&>(h);
}

// ---------------- cp.async helpers (LDGSTS, sm_80+) --------------------------
__device__ __forceinline__ unsigned int smem_u32(const void* p) {
    unsigned int a;
    asm("{ .reg .u64 t; cvta.to.shared.u64 t, %1; cvt.u32.u64 %0, t; }"
        : "=r"(a) : "l"(p));
    return a;
}
__device__ __forceinline__ void cp_async16(unsigned int daddr, const void* src) {
    asm volatile("cp.async.cg.shared.global [%0], [%1], 16;"
                 :: "r"(daddr), "l"(src));
}
__device__ __forceinline__ void cp_commit() {
    asm volatile("cp.async.commit_group;" ::: "memory");
}
template <int N> __device__ __forceinline__ void cp_wait() {
    asm volatile("cp.async.wait_group %0;" :: "n"(N) : "memory");
}

// ---- phase 0: zero counts, bump gen, detect index dtype (tiny) -------------
__global__ void __launch_bounds__(256)
k_setup(const unsigned int* __restrict__ src) {
    int i = blockIdx.x * blockDim.x + threadIdx.x;
    if (i < NMAX) g_cnt[i] = 0;
    if (i == 0) {
        g_ovf_cnt = 0;
        g_gen = g_gen + 1;
        int is64 = 1;
#pragma unroll
        for (int k = 0; k < 8; k++)
            if (src[2 * k + 1] != 0u) is64 = 0;
        g_idx64 = is64;
    }
}

// ---- phase 1: fused fp16-mirror build + dedup + bucket fill ----------------
// Mirror build is DRAM-bound; dedup is latency/atomic-bound -> overlap them
// in one kernel. Thread i: mirror element i (i < n4), edge i (i < nE).
__global__ void __launch_bounds__(256)
k_dedup_fill(const float4* __restrict__ nf,
             const void* __restrict__ srcp, const void* __restrict__ dstp,
             int nE, int n4) {
    int e = blockIdx.x * blockDim.x + threadIdx.x;

    if (e < n4) {                       // fp16 mirror: one float4 -> one uint2
        float4 a = nf[e];
        uint2 o;
        o.x = u32_from_h2(__float22half2_rn(make_float2(a.x, a.y)));
        o.y = u32_from_h2(__float22half2_rn(make_float2(a.z, a.w)));
        g_nf16[e] = o;
    }
    if (e >= nE) return;

    int s, d;
    if (g_idx64) {
        s = (int)((const long long*)srcp)[e];
        d = (int)((const long long*)dstp)[e];
    } else {
        s = ((const int*)srcp)[e];
        d = ((const int*)dstp)[e];
    }

    unsigned int gen = g_gen;
    unsigned int key = ((unsigned)s << 16) | (unsigned)d;
    unsigned long long want = ((unsigned long long)gen << 32) | key;
    unsigned int slot = (key * 0x9E3779B1u) >> (32 - 21);

    for (;;) {
        unsigned long long cur;
        asm volatile("ld.global.cg.u64 %0, [%1];"
                     : "=l"(cur) : "l"(&g_hash[slot]));
        if (cur == want) return;
        if ((unsigned int)(cur >> 32) != gen) {
            unsigned long long prev = atomicCAS(&g_hash[slot], cur, want);
            if (prev == cur) break;
            if (prev == want) return;
            if ((unsigned int)(prev >> 32) != gen) continue;
        }
        slot = (slot + 1) & (HASH_SIZE - 1);
    }
    int pos = atomicAdd(&g_cnt[d], 1);
    if (pos < PAD) {
        g_bucket[(size_t)d * PAD + pos] = s;
    } else {
        int o = atomicAdd(&g_ovf_cnt, 1);
        if (o < OVF_MAX) { g_ovf[2 * o] = s; g_ovf[2 * o + 1] = d; }
    }
}

// ---- phase 2: warp-per-dst fp16 gather-sum + (1+alpha)*x + fused overflow --
__global__ void __launch_bounds__(256)
k_agg(const float* __restrict__ nfeats, const float* __restrict__ alpha,
      int nrows) {
    int w = (int)((blockIdx.x * 256u + threadIdx.x) >> 5);
    int lane = threadIdx.x & 31;
    if (w >= nrows) return;

    const float4* nf4 = (const float4*)nfeats;
    float sc = 1.0f + alpha[0];

    float4 a = nf4[(size_t)w * 32 + lane];
    float4 acc = make_float4(a.x * sc, a.y * sc, a.z * sc, a.w * sc);

    int cnt = g_cnt[w];
    if (cnt > PAD) cnt = PAD;
    const int* bk = &g_bucket[(size_t)w * PAD];

#define ACC_H8(u)                                                         \
    do {                                                                  \
        float2 f0 = __half22float2(h2_from_u32((u).x));                   \
        float2 f1 = __half22float2(h2_from_u32((u).y));                   \
        acc.x += f0.x; acc.y += f0.y; acc.z += f1.x; acc.w += f1.y;       \
    } while (0)

    int j = 0;
    for (; j + 4 <= cnt; j += 4) {
        int s0 = bk[j], s1 = bk[j + 1], s2 = bk[j + 2], s3 = bk[j + 3];
        uint2 v0 = g_nf16[(size_t)s0 * 32 + lane];
        uint2 v1 = g_nf16[(size_t)s1 * 32 + lane];
        uint2 v2 = g_nf16[(size_t)s2 * 32 + lane];
        uint2 v3 = g_nf16[(size_t)s3 * 32 + lane];
        ACC_H8(v0); ACC_H8(v1); ACC_H8(v2); ACC_H8(v3);
    }
    for (; j < cnt; j++) {
        uint2 v0 = g_nf16[(size_t)bk[j] * 32 + lane];
        ACC_H8(v0);
    }
#undef ACC_H8

    int novf = g_ovf_cnt;
    if (novf > 0) {
        if (novf > OVF_MAX) novf = OVF_MAX;
        for (int k = 0; k < novf; k++) {
            if (g_ovf[2 * k + 1] == w) {
                int s = g_ovf[2 * k];
                float4 u = nf4[(size_t)s * 32 + lane];
                acc.x += u.x; acc.y += u.y; acc.z += u.z; acc.w += u.w;
            }
        }
    }

    ((float4*)g_h)[(size_t)w * 32 + lane] = acc;
}

// ---- phase 3: fused 2-layer MLP, cp.async double-buffered W staging --------
// smem: sWa 32K + sWb 32K + sH 16K + sH1 32K = 112KB -> 2 blocks/SM.
#define MLP_INNER(SW, HROW, STRIDE)                                        \
    _Pragma("unroll 2")                                                    \
    for (int k0 = 0; k0 < 64; k0 += 4) {                                   \
        float4 h4[8];                                                      \
        _Pragma("unroll")                                                  \
        for (int i = 0; i < 8; i++)                                        \
            h4[i] = *(const float4*)((HROW) + i * (STRIDE) + k0);          \
        _Pragma("unroll")                                                  \
        for (int kk = 0; kk < 4; kk++) {                                   \
            ulonglong2 wv =                                                \
                *(const ulonglong2*)((SW) + (k0 + kk) * D + x * 4);        \
            _Pragma("unroll")                                              \
            for (int i = 0; i < 8; i++) {                                  \
                float hk = (&h4[i].x)[kk];                                 \
                unsigned long long h2 = pack2(hk, hk);                     \
                a01[i] = ffma2(h2, wv.x, a01[i]);                          \
                a23[i] = ffma2(h2, wv.y, a23[i]);                          \
            }                                                              \
        }                                                                  \
    }

__device__ __forceinline__ void cpW(float* dst, const float* src, int tid) {
    unsigned int d0 = smem_u32(dst);
    const float4* s4 = (const float4*)src;
#pragma unroll
    for (int i = 0; i < 8; i++)
        cp_async16(d0 + (tid + 256 * i) * 16, &s4[tid + 256 * i]);
}
__device__ __forceinline__ void cpH(float* dst, const float* gin, int row0,
                                    int koff, int tid) {
    unsigned int d0 = smem_u32(dst);
#pragma unroll
    for (int j = 0; j < 4; j++) {
        int i = tid + 256 * j;
        int r = i >> 4, c4 = i & 15;
        cp_async16(d0 + i * 16,
                   gin + (size_t)(row0 + r) * D + koff + c4 * 4);
    }
}

__global__ void __launch_bounds__(256)
k_mlp(const float* __restrict__ W1, const float* __restrict__ b1,
      const float* __restrict__ W2, const float* __restrict__ b2,
      float* __restrict__ out, int nrows) {
    extern __shared__ float smem[];
    float* sWa = smem;                 // 8192 floats
    float* sWb = smem + 8192;          // 8192 floats
    float* sH  = smem + 16384;         // 4096 floats (64 rows x 64 k)
    float* sH1 = smem + 20480;         // 8192 floats (64 rows x 128 cols)

    int tid = threadIdx.x;
    int x = tid & 31;
    int y = tid >> 5;
    int row0 = blockIdx.x * 64;

    // g0: sWa <- W1h0 + sH <- Hh0 ; g1: sWb <- W1h1
    cpW(sWa, W1, tid);
    cpH(sH, g_h, row0, 0, tid);
    cp_commit();
    cpW(sWb, W1 + 64 * D, tid);
    cp_commit();

    unsigned long long a01[8], a23[8];
    {
        float4 bv = *(const float4*)(b1 + x * 4);
        unsigned long long i01 = pack2(bv.x, bv.y), i23 = pack2(bv.z, bv.w);
#pragma unroll
        for (int i = 0; i < 8; i++) { a01[i] = i01; a23[i] = i23; }
    }

    cp_wait<1>();              // g0 done (sWa, sH)
    __syncthreads();
    {   // layer 1, phase 0 (sWa, sH); sWb streaming in background
        const float* hrow = sH + y * 8 * 64;
        MLP_INNER(sWa, hrow, 64)
    }
    cp_wait<0>();              // g1 done (sWb)
    __syncthreads();           // all warps done reading sH & sWa

    // g2: sH <- Hh1 ; g3: sWa <- W2h0 (background for layer 2)
    cpH(sH, g_h, row0, 64, tid);
    cp_commit();
    cpW(sWa, W2, tid);
    cp_commit();
    cp_wait<1>();              // g2 done (sH refilled); g3 in flight
    __syncthreads();
    {   // layer 1, phase 1 (sWb, sH)
        const float* hrow = sH + y * 8 * 64;
        MLP_INNER(sWb, hrow, 64)
    }

    // epilogue layer 1 -> sH1 (own rows; read back by same warp)
#pragma unroll
    for (int i = 0; i < 8; i++) {
        float f0, f1, f2, f3;
        unpack2(a01[i], f0, f1); unpack2(a23[i], f2, f3);
        *(float4*)(sH1 + (y * 8 + i) * D + x * 4) =
            make_float4(fmaxf(f0, 0.f), fmaxf(f1, 0.f),
                        fmaxf(f2, 0.f), fmaxf(f3, 0.f));
    }
    __syncwarp();

    {
        float4 bv = *(const float4*)(b2 + x * 4);
        unsigned long long i01 = pack2(bv.x, bv.y), i23 = pack2(bv.z, bv.w);
#pragma unroll
        for (int i = 0; i < 8; i++) { a01[i] = i01; a23[i] = i23; }
    }

    cp_wait<0>();              // g3 done (sWa = W2h0)
    __syncthreads();           // all warps done reading sWb (layer-1 ph1)
    // g4: sWb <- W2h1 (background)
    cpW(sWb, W2 + 64 * D, tid);
    cp_commit();
    {   // layer 2, phase 0 (sWa, sH1 cols 0..64)
        const float* hrow = sH1 + y * 8 * D;
        MLP_INNER(sWa, hrow, D)
    }
    cp_wait<0>();              // g4 done (sWb = W2h1)
    __syncthreads();
    {   // layer 2, phase 1 (sWb, sH1 cols 64..128)
        const float* hrow = sH1 + y * 8 * D + 64;
        MLP_INNER(sWb, hrow, D)
    }

#pragma unroll
    for (int i = 0; i < 8; i++) {
        int gr = row0 + y * 8 + i;
        if (gr < nrows) {
            float f0, f1, f2, f3;
            unpack2(a01[i], f0, f1); unpack2(a23[i], f2, f3);
            *(float4*)(out + (size_t)gr * D + x * 4) =
                make_float4(f0, f1, f2, f3);
        }
    }
}

// ---------------- launch ----------------------------------------------------
#define MLP_SMEM (28672 * 4)     // 114688 bytes

extern "C" void kernel_launch(void* const* d_in, const int* in_sizes, int n_in,
                              void* d_out, int out_size) {
    const float* nfeats = (const float*)d_in[0];
    const void*  src    = d_in[1];
    const void*  dst    = d_in[2];
    const float* W1     = (const float*)d_in[3];
    const float* b1     = (const float*)d_in[4];
    const float* W2     = (const float*)d_in[5];
    const float* b2     = (const float*)d_in[6];
    const float* alpha  = (const float*)d_in[7];
    float* out = (float*)d_out;

    int nE    = in_sizes[1];
    int nrows = in_sizes[0] / D;
    int n4    = nrows * (D / 4);

    k_setup<<<(NMAX + 255) / 256, 256>>>((const unsigned int*)src);

    int work = n4 > nE ? n4 : nE;
    k_dedup_fill<<<(work + 255) / 256, 256>>>(
        (const float4*)nfeats, src, dst, nE, n4);

    k_agg<<<(nrows + 7) / 8, 256>>>(nfeats, alpha, nrows);

    cudaFuncSetAttribute(k_mlp, cudaFuncAttributeMaxDynamicSharedMemorySize,
                         MLP_SMEM);
    int nblk = (nrows + 63) / 64;
    k_mlp<<<nblk, 256, MLP_SMEM>>>(W1, b1, W2, b2, out, nrows);
}